// round 15
// baseline (speedup 1.0000x reference)
#include <cuda_runtime.h>
#include <cuda_fp16.h>
#include <cstdint>

#define NN      100000
#define DIM     256
#define NRELS   8
#define EPR     160000
#define NEDGES  (NRELS * EPR)
#define NBINS   (NRELS * NN)

#define KTOT    2304              // 8 relations * 256 + self 256
#define TM      128               // dst rows per block
#define NZ      9                 // 8 relations + self
#define NCHTOT  36                // 9 * 4 K-chunks of 64 halves
#define NTHR    384               // 8 MMA warps + 4 agg warps

// ---- smem layout ----
// A aggregate buffers: 128 rows x 132 words (256 halves + 8 pad halves)
#define AG_STRIDE 132                       // words per row
#define AG_BYTES  (TM * AG_STRIDE * 4)      // 67584
#define OFF_AG0   0
#define OFF_AG1   AG_BYTES
// B staging: 256 n-rows x 36 words (64 halves + 8 pad)
#define B_STRIDE  36
#define B_BYTES   (DIM * B_STRIDE * 4)      // 36864
#define OFF_B0    (2 * AG_BYTES)            // 135168
#define OFF_B1    (OFF_B0 + B_BYTES)        // 172032
#define SMEM_TOTAL (OFF_B1 + B_BYTES)       // 208896 -> 1 CTA/SM
// C-tile staging for fused LN (reuses AG region): 128 x 260 floats = 133120 B
#define CS_STRIDE 260

#define SCAN_BLK 1024
#define NSCANBLK ((NBINS + SCAN_BLK - 1) / SCAN_BLK)   // 782

// ---------------------------------------------------------------------------
// device scratch
// ---------------------------------------------------------------------------
__device__ int     g_src32[NEDGES];             // src sorted by (rel, dst)
__device__ int     g_idx_is_i32;
__device__ int     g_off[NBINS];                // end offsets (post-scatter)
__device__ int     g_off0[NBINS];               // start offsets
__device__ int     g_bsum[SCAN_BLK];
__device__ __half2 g_xh[NN * DIM / 2];          // x -> fp16 (51.2MB, L2-resident)
__device__ __half  g_Wbig[DIM * KTOT];          // [n][2304]: {W_rel 0..7, W_self}

// ---------------------------------------------------------------------------
// helpers
// ---------------------------------------------------------------------------
__device__ __forceinline__ void mma_f16(float c[4], const unsigned a[4], const unsigned b[2]) {
    asm volatile(
        "mma.sync.aligned.m16n8k16.row.col.f32.f16.f16.f32 "
        "{%0,%1,%2,%3}, {%4,%5,%6,%7}, {%8,%9}, {%0,%1,%2,%3};\n"
        : "+f"(c[0]), "+f"(c[1]), "+f"(c[2]), "+f"(c[3])
        : "r"(a[0]), "r"(a[1]), "r"(a[2]), "r"(a[3]), "r"(b[0]), "r"(b[1]));
}

__device__ __forceinline__ void cp_async16(uint32_t saddr, const void* g) {
    asm volatile("cp.async.cg.shared.global [%0], [%1], 16;" :: "r"(saddr), "l"(g) : "memory");
}
__device__ __forceinline__ void cp_commit() { asm volatile("cp.async.commit_group;" ::: "memory"); }
__device__ __forceinline__ void cp_wait1()  { asm volatile("cp.async.wait_group 1;" ::: "memory"); }
__device__ __forceinline__ void barn(int id, int cnt) {
    asm volatile("bar.sync %0, %1;" :: "r"(id), "r"(cnt) : "memory");
}

__device__ __forceinline__ int load_idx(const void* buf, long long i) {
    return g_idx_is_i32 ? ((const int*)buf)[i] : (int)((const long long*)buf)[i];
}

// ---------------------------------------------------------------------------
// prepass: dtype detect + counting sort of src by (rel, dst)
// ---------------------------------------------------------------------------
__global__ void detect_idx_kernel(const void* srcbuf) {
    const long long* p = (const long long*)srcbuf;
    int tid = threadIdx.x;
    int bad = 0;
    #pragma unroll
    for (int i = 0; i < 4; i++) {
        long long v = p[tid * 4 + i];
        if (v < 0 || v >= NN) bad = 1;
    }
    int any = __syncthreads_or(bad);
    if (tid == 0) g_idx_is_i32 = any;
}

__global__ void zero_hist_kernel() {
    int i = blockIdx.x * blockDim.x + threadIdx.x;
    if (i < NBINS) g_off[i] = 0;
}

__global__ void hist_kernel(const void* dstbuf) {
    long long i = (long long)blockIdx.x * blockDim.x + threadIdx.x;
    if (i >= NEDGES) return;
    int rel = (int)(i / EPR);
    int dst = load_idx(dstbuf, i);
    atomicAdd(&g_off[rel * NN + dst], 1);
}

__global__ void scan_local_kernel() {
    __shared__ int sh[SCAN_BLK];
    int i = blockIdx.x * SCAN_BLK + threadIdx.x;
    int v = (i < NBINS) ? g_off[i] : 0;
    sh[threadIdx.x] = v;
    __syncthreads();
    #pragma unroll
    for (int o = 1; o < SCAN_BLK; o <<= 1) {
        int t = (threadIdx.x >= o) ? sh[threadIdx.x - o] : 0;
        __syncthreads();
        sh[threadIdx.x] += t;
        __syncthreads();
    }
    if (i < NBINS) g_off[i] = sh[threadIdx.x] - v;   // exclusive
    if (threadIdx.x == SCAN_BLK - 1) g_bsum[blockIdx.x] = sh[threadIdx.x];
}

__global__ void scan_bsum_kernel() {
    __shared__ int sh[SCAN_BLK];
    int v = (threadIdx.x < NSCANBLK) ? g_bsum[threadIdx.x] : 0;
    sh[threadIdx.x] = v;
    __syncthreads();
    #pragma unroll
    for (int o = 1; o < SCAN_BLK; o <<= 1) {
        int t = (threadIdx.x >= o) ? sh[threadIdx.x - o] : 0;
        __syncthreads();
        sh[threadIdx.x] += t;
        __syncthreads();
    }
    if (threadIdx.x < NSCANBLK) g_bsum[threadIdx.x] = sh[threadIdx.x] - v;
}

__global__ void add_bsum_kernel() {
    int i = blockIdx.x * SCAN_BLK + threadIdx.x;
    if (i < NBINS) g_off[i] += g_bsum[blockIdx.x];
}

__global__ void copy_off_kernel() {
    int i = blockIdx.x * blockDim.x + threadIdx.x;
    if (i < NBINS) g_off0[i] = g_off[i];   // start offsets (pre-scatter)
}

__global__ void scatter_kernel(const void* srcbuf, const void* dstbuf) {
    long long i = (long long)blockIdx.x * blockDim.x + threadIdx.x;
    if (i >= NEDGES) return;
    int rel = (int)(i / EPR);
    int src = load_idx(srcbuf, i);
    int dst = load_idx(dstbuf, i);
    int pos = atomicAdd(&g_off[rel * NN + dst], 1);   // bumps to end offsets
    g_src32[pos] = src;
}

// ---------------------------------------------------------------------------
// conversions
// ---------------------------------------------------------------------------
__global__ void x_to_half(const float* __restrict__ x) {
    long long i = (long long)blockIdx.x * blockDim.x + threadIdx.x;
    if (i >= (long long)NN * DIM / 2) return;
    float2 v = ((const float2*)x)[i];
    g_xh[i] = __floats2half2_rn(v.x, v.y);
}

// Wbig[n][z*256 + k] = W_z[k][n];  z = 0..7 -> W_rel[z], z = 8 -> W_self
__global__ void build_wbig(const float* __restrict__ Wrel, const float* __restrict__ Wself) {
    __shared__ float t[32][33];
    int z = blockIdx.z;
    const float* S = (z < NRELS) ? (Wrel + (size_t)z * DIM * DIM) : Wself;
    int bn = blockIdx.x * 32, bk = blockIdx.y * 32;
    t[threadIdx.y][threadIdx.x] = S[(size_t)(bk + threadIdx.y) * DIM + bn + threadIdx.x];
    __syncthreads();
    int n = bn + threadIdx.y, k = bk + threadIdx.x;
    g_Wbig[(size_t)n * KTOT + z * DIM + k] = __float2half_rn(t[threadIdx.x][threadIdx.y]);
}

// ---------------------------------------------------------------------------
// Fused RGCN kernel: per block, 128 consecutive dst rows.
// Warps 0-7 (tid<256): fp16 MMA, warp tile M64xN64 (128 accum regs), over 9
// relation-slices consuming double-buffered aggregate A_z.
// Warps 8-11: aggregate relation z+1 (CSR sums, 32 rows/warp) during MMA of z.
// Epilogue: C staged to smem, LayerNorm fused, normalized rows stored direct.
// No atomics anywhere.
// ---------------------------------------------------------------------------
__global__ __launch_bounds__(NTHR, 1)
void fused_rgcn(const __half* __restrict__ XH,
                const __half* __restrict__ WB,
                float* __restrict__ out,
                const float* __restrict__ gamma,
                const float* __restrict__ beta)
{
    extern __shared__ char smem[];
    const int tid = threadIdx.x;
    const long long base = (long long)blockIdx.x * TM;

    uint32_t sb;
    asm("{ .reg .u64 t; cvta.to.shared.u64 t, %1; cvt.u32.u64 %0, t; }" : "=r"(sb) : "l"(smem));

    const int lane = tid & 31;
    const int warp = tid >> 5;

    // ---- aggregation (warps 8..11): fill A buffer (zz&1) with relation zz ----
    auto aggregate = [&](int zz) {
        const int awarp = warp - 8;                   // 0..3
        char* Ag = smem + ((zz & 1) ? OFF_AG1 : OFF_AG0);
        #pragma unroll 1
        for (int rr = 0; rr < 32; rr++) {
            int r = awarp * 32 + rr;
            long long d = base + r;
            float acc[8] = {0.f, 0.f, 0.f, 0.f, 0.f, 0.f, 0.f, 0.f};
            if (d < NN) {
                if (zz < 8) {
                    int bin = zz * NN + (int)d;
                    int e0 = g_off0[bin], e1 = g_off[bin];
                    for (int e = e0; e < e1; e++) {
                        int src = g_src32[e];
                        uint4 v = *reinterpret_cast<const uint4*>(
                            (const char*)XH + (size_t)src * 512 + lane * 16);
                        const __half2* h = reinterpret_cast<const __half2*>(&v);
                        #pragma unroll
                        for (int i = 0; i < 4; i++) {
                            float2 f = __half22float2(h[i]);
                            acc[2 * i]     += f.x;
                            acc[2 * i + 1] += f.y;
                        }
                    }
                } else {   // self: copy x[d]
                    uint4 v = *reinterpret_cast<const uint4*>(
                        (const char*)XH + (size_t)d * 512 + lane * 16);
                    const __half2* h = reinterpret_cast<const __half2*>(&v);
                    #pragma unroll
                    for (int i = 0; i < 4; i++) {
                        float2 f = __half22float2(h[i]);
                        acc[2 * i]     += f.x;
                        acc[2 * i + 1] += f.y;
                    }
                }
            }
            __half2 o[4];
            #pragma unroll
            for (int i = 0; i < 4; i++) o[i] = __floats2half2_rn(acc[2 * i], acc[2 * i + 1]);
            *reinterpret_cast<uint4*>(Ag + (size_t)(r * AG_STRIDE + lane * 4) * 4) =
                *reinterpret_cast<const uint4*>(o);
        }
    };

    // ---- MMA-side identifiers (warps 0..7): wm in {0,1} covers M=64 each ----
    const int wm = warp >> 2;
    const int wn = warp & 3;
    const int g  = lane >> 2;
    const int t4 = lane & 3;

    const char* bSrc = (const char*)WB + (size_t)tid * (KTOT * 2);   // used for tid<256
    const uint32_t offB[2] = { sb + OFF_B0, sb + OFF_B1 };

    auto stageB = [&](int kc, int buf) {   // kc = global chunk 0..35 (tid<256 only)
        #pragma unroll
        for (int i = 0; i < 8; i++)
            cp_async16(offB[buf] + tid * (B_STRIDE * 4) + i * 16, bSrc + kc * 128 + i * 16);
    };

    float c[4][8][4];
    #pragma unroll
    for (int mi = 0; mi < 4; mi++)
        #pragma unroll
        for (int j = 0; j < 8; j++)
            #pragma unroll
            for (int q = 0; q < 4; q++)
                c[mi][j][q] = 0.f;

    // ---- prologue ----
    if (tid < 256) {
        stageB(0, 0);
        cp_commit();
    } else {
        aggregate(0);                  // A_0 into buffer 0
    }
    __syncthreads();

    // ---- main loop over relation slices ----
    #pragma unroll 1
    for (int z = 0; z < NZ; z++) {
        if (tid < 256) {
            const unsigned* Ab = (const unsigned*)(smem + ((z & 1) ? OFF_AG1 : OFF_AG0));
            #pragma unroll 1
            for (int kc4 = 0; kc4 < 4; kc4++) {
                const int kc = z * 4 + kc4;
                if (kc + 1 < NCHTOT) stageB(kc + 1, (kc + 1) & 1);
                cp_commit();           // uniform group accounting
                cp_wait1();            // chunk kc's group complete
                barn(1, 256);          // visible to all MMA warps

                const unsigned* Bb = (const unsigned*)(smem + ((kc & 1) ? OFF_B1 : OFF_B0));
                const int abase = kc4 * 32;

                #pragma unroll
                for (int s = 0; s < 4; s++) {
                    unsigned b[8][2];
                    #pragma unroll
                    for (int j = 0; j < 8; j++) {
                        int n = wn * 64 + j * 8 + g;
                        b[j][0] = Bb[(size_t)n * B_STRIDE + s * 8 + t4];
                        b[j][1] = Bb[(size_t)n * B_STRIDE + s * 8 + t4 + 4];
                    }
                    #pragma unroll
                    for (int mi = 0; mi < 4; mi++) {
                        unsigned a[4];
                        int rb = wm * 64 + mi * 16 + g;
                        a[0] = Ab[(size_t)rb       * AG_STRIDE + abase + s * 8 + t4];
                        a[1] = Ab[(size_t)(rb + 8) * AG_STRIDE + abase + s * 8 + t4];
                        a[2] = Ab[(size_t)rb       * AG_STRIDE + abase + s * 8 + t4 + 4];
                        a[3] = Ab[(size_t)(rb + 8) * AG_STRIDE + abase + s * 8 + t4 + 4];
                        #pragma unroll
                        for (int j = 0; j < 8; j++)
                            mma_f16(c[mi][j], a, b[j]);
                    }
                }
                barn(1, 256);          // all MMA warps done reading B buf (WAR)
            }
        } else {
            if (z + 1 < NZ) aggregate(z + 1);   // next relation (or self) into other A buf
        }
        __syncthreads();               // A handoff for z+1
    }

    // ---- epilogue: stage C to smem (AG region now free), fused LayerNorm ----
    float* Cs = (float*)smem;          // [TM][CS_STRIDE]
    if (tid < 256) {
        #pragma unroll
        for (int mi = 0; mi < 4; mi++) {
            #pragma unroll
            for (int half = 0; half < 2; half++) {
                int r = wm * 64 + mi * 16 + half * 8 + g;
                float* rowp = Cs + (size_t)r * CS_STRIDE + wn * 64;
                #pragma unroll
                for (int j = 0; j < 8; j++) {
                    int col = j * 8 + t4 * 2;
                    *reinterpret_cast<float2*>(rowp + col) =
                        make_float2(c[mi][j][half * 2 + 0], c[mi][j][half * 2 + 1]);
                }
            }
        }
    }
    __syncthreads();

    // LayerNorm: 12 warps cover 128 rows
    {
        float4 g0 = *reinterpret_cast<const float4*>(gamma + lane * 4);
        float4 g1 = *reinterpret_cast<const float4*>(gamma + 128 + lane * 4);
        float4 b0 = *reinterpret_cast<const float4*>(beta + lane * 4);
        float4 b1 = *reinterpret_cast<const float4*>(beta + 128 + lane * 4);

        #pragma unroll 1
        for (int r = warp; r < TM; r += 12) {
            long long drow = base + r;
            if (drow >= NN) continue;
            const float* row = Cs + (size_t)r * CS_STRIDE;
            float4 v0 = *reinterpret_cast<const float4*>(row + lane * 4);
            float4 v1 = *reinterpret_cast<const float4*>(row + 128 + lane * 4);

            float s  = v0.x + v0.y + v0.z + v0.w + v1.x + v1.y + v1.z + v1.w;
            float sq = fmaf(v0.x, v0.x, fmaf(v0.y, v0.y, fmaf(v0.z, v0.z, v0.w * v0.w)))
                     + fmaf(v1.x, v1.x, fmaf(v1.y, v1.y, fmaf(v1.z, v1.z, v1.w * v1.w)));
            #pragma unroll
            for (int o = 16; o; o >>= 1) {
                s  += __shfl_xor_sync(0xffffffffu, s,  o);
                sq += __shfl_xor_sync(0xffffffffu, sq, o);
            }
            float mean = s * (1.f / 256.f);
            float var  = sq * (1.f / 256.f) - mean * mean;
            float rs   = rsqrtf(var + 1e-5f);

            float4 o0, o1;
            o0.x = (v0.x - mean) * rs * g0.x + b0.x;
            o0.y = (v0.y - mean) * rs * g0.y + b0.y;
            o0.z = (v0.z - mean) * rs * g0.z + b0.z;
            o0.w = (v0.w - mean) * rs * g0.w + b0.w;
            o1.x = (v1.x - mean) * rs * g1.x + b1.x;
            o1.y = (v1.y - mean) * rs * g1.y + b1.y;
            o1.z = (v1.z - mean) * rs * g1.z + b1.z;
            o1.w = (v1.w - mean) * rs * g1.w + b1.w;

            float* op = out + (size_t)drow * DIM;
            *reinterpret_cast<float4*>(op + lane * 4)       = o0;
            *reinterpret_cast<float4*>(op + 128 + lane * 4) = o1;
        }
    }
}

extern "C" void kernel_launch(void* const* d_in, const int* in_sizes, int n_in,
                              void* d_out, int out_size)
{
    const float* x     = (const float*)d_in[0];
    const void*  srcb  = d_in[1];
    const void*  dstb  = d_in[2];
    const float* Wself = (const float*)d_in[3];
    const float* Wrel  = (const float*)d_in[4];
    const float* gamma = (const float*)d_in[5];
    const float* beta  = (const float*)d_in[6];
    float* out = (float*)d_out;

    void *pXh = nullptr, *pWB = nullptr;
    cudaGetSymbolAddress(&pXh, g_xh);
    cudaGetSymbolAddress(&pWB, g_Wbig);

    cudaFuncSetAttribute(fused_rgcn,
                         cudaFuncAttributeMaxDynamicSharedMemorySize, SMEM_TOTAL);

    // --- prepass: dtype detect + counting sort of src by (rel, dst) ---
    detect_idx_kernel<<<1, 256>>>(srcb);
    zero_hist_kernel<<<(NBINS + 1023) / 1024, 1024>>>();
    hist_kernel<<<(NEDGES + 255) / 256, 256>>>(dstb);
    scan_local_kernel<<<NSCANBLK, SCAN_BLK>>>();
    scan_bsum_kernel<<<1, SCAN_BLK>>>();
    add_bsum_kernel<<<NSCANBLK, SCAN_BLK>>>();
    copy_off_kernel<<<(NBINS + 1023) / 1024, 1024>>>();
    scatter_kernel<<<(NEDGES + 255) / 256, 256>>>(srcb, dstb);

    // --- conversions ---
    {
        long long nh2 = (long long)NN * DIM / 2;
        x_to_half<<<(int)((nh2 + 255) / 256), 256>>>(x);
        build_wbig<<<dim3(8, 8, NRELS + 1), dim3(32, 32)>>>(Wrel, Wself);
    }

    // --- fused aggregate + GEMM + LayerNorm ---
    fused_rgcn<<<(NN + TM - 1) / TM, NTHR, SMEM_TOTAL>>>(
        (const __half*)pXh, (const __half*)pWB, out, gamma, beta);
}

// round 16
// speedup vs baseline: 1.4311x; 1.4311x over previous
#include <cuda_runtime.h>
#include <cuda_fp16.h>
#include <cstdint>

#define NN      100000
#define DIM     256
#define NRELS   8
#define EPR     160000
#define NEDGES  (NRELS * EPR)
#define NBINS   (NRELS * NN)

#define KTOT    2304              // 8 relations * 256 + self 256
#define TM      64                // dst rows per block
#define NZ      9                 // 8 relations + self
#define NCHTOT  36                // 9 * 4 K-chunks of 64 halves

// ---- smem layout ----
// A aggregate buffers: 64 rows x 132 words (256 halves + 8 pad halves)
#define AG_STRIDE 132                       // words per row
#define AG_BYTES  (TM * AG_STRIDE * 4)      // 33792
#define OFF_AG0   0
#define OFF_AG1   AG_BYTES
// B staging: 256 n-rows x 36 words (64 halves + 8 pad)
#define B_STRIDE  36
#define B_BYTES   (DIM * B_STRIDE * 4)      // 36864
#define OFF_B0    (2 * AG_BYTES)            // 67584
#define OFF_B1    (OFF_B0 + B_BYTES)        // 104448
#define SMEM_TOTAL (OFF_B1 + B_BYTES)       // 141312 -> 1 CTA/SM
// C-tile staging for fused LN (reuses AG region): 64 x 260 floats = 66560 B
#define CS_STRIDE 260

#define SCAN_BLK 1024
#define NSCANBLK ((NBINS + SCAN_BLK - 1) / SCAN_BLK)   // 782

// ---------------------------------------------------------------------------
// device scratch
// ---------------------------------------------------------------------------
__device__ int     g_src32[NEDGES];             // src sorted by (rel, dst)
__device__ int     g_idx_is_i32;
__device__ int     g_off[NBINS];                // end offsets (post-scatter)
__device__ int     g_off0[NBINS];               // start offsets
__device__ int     g_bsum[SCAN_BLK];
__device__ __half2 g_xh[NN * DIM / 2];          // x -> fp16 (51.2MB, L2-resident)
__device__ __half  g_Wbig[DIM * KTOT];          // [n][2304]: {W_rel 0..7, W_self}

// ---------------------------------------------------------------------------
// helpers
// ---------------------------------------------------------------------------
__device__ __forceinline__ void mma_f16(float c[4], const unsigned a[4], const unsigned b[2]) {
    asm volatile(
        "mma.sync.aligned.m16n8k16.row.col.f32.f16.f16.f32 "
        "{%0,%1,%2,%3}, {%4,%5,%6,%7}, {%8,%9}, {%0,%1,%2,%3};\n"
        : "+f"(c[0]), "+f"(c[1]), "+f"(c[2]), "+f"(c[3])
        : "r"(a[0]), "r"(a[1]), "r"(a[2]), "r"(a[3]), "r"(b[0]), "r"(b[1]));
}

__device__ __forceinline__ void cp_async16(uint32_t saddr, const void* g) {
    asm volatile("cp.async.cg.shared.global [%0], [%1], 16;" :: "r"(saddr), "l"(g) : "memory");
}
__device__ __forceinline__ void cp_commit() { asm volatile("cp.async.commit_group;" ::: "memory"); }
__device__ __forceinline__ void cp_wait1()  { asm volatile("cp.async.wait_group 1;" ::: "memory"); }
__device__ __forceinline__ void barn(int id, int cnt) {
    asm volatile("bar.sync %0, %1;" :: "r"(id), "r"(cnt) : "memory");
}

__device__ __forceinline__ int load_idx(const void* buf, long long i) {
    return g_idx_is_i32 ? ((const int*)buf)[i] : (int)((const long long*)buf)[i];
}

// ---------------------------------------------------------------------------
// prepass: dtype detect + counting sort of src by (rel, dst)
// ---------------------------------------------------------------------------
__global__ void detect_idx_kernel(const void* srcbuf) {
    const long long* p = (const long long*)srcbuf;
    int tid = threadIdx.x;
    int bad = 0;
    #pragma unroll
    for (int i = 0; i < 4; i++) {
        long long v = p[tid * 4 + i];
        if (v < 0 || v >= NN) bad = 1;
    }
    int any = __syncthreads_or(bad);
    if (tid == 0) g_idx_is_i32 = any;
}

__global__ void zero_hist_kernel() {
    int i = blockIdx.x * blockDim.x + threadIdx.x;
    if (i < NBINS) g_off[i] = 0;
}

__global__ void hist_kernel(const void* dstbuf) {
    long long i = (long long)blockIdx.x * blockDim.x + threadIdx.x;
    if (i >= NEDGES) return;
    int rel = (int)(i / EPR);
    int dst = load_idx(dstbuf, i);
    atomicAdd(&g_off[rel * NN + dst], 1);
}

__global__ void scan_local_kernel() {
    __shared__ int sh[SCAN_BLK];
    int i = blockIdx.x * SCAN_BLK + threadIdx.x;
    int v = (i < NBINS) ? g_off[i] : 0;
    sh[threadIdx.x] = v;
    __syncthreads();
    #pragma unroll
    for (int o = 1; o < SCAN_BLK; o <<= 1) {
        int t = (threadIdx.x >= o) ? sh[threadIdx.x - o] : 0;
        __syncthreads();
        sh[threadIdx.x] += t;
        __syncthreads();
    }
    if (i < NBINS) g_off[i] = sh[threadIdx.x] - v;   // exclusive
    if (threadIdx.x == SCAN_BLK - 1) g_bsum[blockIdx.x] = sh[threadIdx.x];
}

__global__ void scan_bsum_kernel() {
    __shared__ int sh[SCAN_BLK];
    int v = (threadIdx.x < NSCANBLK) ? g_bsum[threadIdx.x] : 0;
    sh[threadIdx.x] = v;
    __syncthreads();
    #pragma unroll
    for (int o = 1; o < SCAN_BLK; o <<= 1) {
        int t = (threadIdx.x >= o) ? sh[threadIdx.x - o] : 0;
        __syncthreads();
        sh[threadIdx.x] += t;
        __syncthreads();
    }
    if (threadIdx.x < NSCANBLK) g_bsum[threadIdx.x] = sh[threadIdx.x] - v;
}

__global__ void add_bsum_kernel() {
    int i = blockIdx.x * SCAN_BLK + threadIdx.x;
    if (i < NBINS) g_off[i] += g_bsum[blockIdx.x];
}

__global__ void copy_off_kernel() {
    int i = blockIdx.x * blockDim.x + threadIdx.x;
    if (i < NBINS) g_off0[i] = g_off[i];   // start offsets (pre-scatter)
}

__global__ void scatter_kernel(const void* srcbuf, const void* dstbuf) {
    long long i = (long long)blockIdx.x * blockDim.x + threadIdx.x;
    if (i >= NEDGES) return;
    int rel = (int)(i / EPR);
    int src = load_idx(srcbuf, i);
    int dst = load_idx(dstbuf, i);
    int pos = atomicAdd(&g_off[rel * NN + dst], 1);   // bumps to end offsets
    g_src32[pos] = src;
}

// ---------------------------------------------------------------------------
// conversions
// ---------------------------------------------------------------------------
__global__ void x_to_half(const float* __restrict__ x) {
    long long i = (long long)blockIdx.x * blockDim.x + threadIdx.x;
    if (i >= (long long)NN * DIM / 2) return;
    float2 v = ((const float2*)x)[i];
    g_xh[i] = __floats2half2_rn(v.x, v.y);
}

// Wbig[n][z*256 + k] = W_z[k][n];  z = 0..7 -> W_rel[z], z = 8 -> W_self
__global__ void build_wbig(const float* __restrict__ Wrel, const float* __restrict__ Wself) {
    __shared__ float t[32][33];
    int z = blockIdx.z;
    const float* S = (z < NRELS) ? (Wrel + (size_t)z * DIM * DIM) : Wself;
    int bn = blockIdx.x * 32, bk = blockIdx.y * 32;
    t[threadIdx.y][threadIdx.x] = S[(size_t)(bk + threadIdx.y) * DIM + bn + threadIdx.x];
    __syncthreads();
    int n = bn + threadIdx.y, k = bk + threadIdx.x;
    g_Wbig[(size_t)n * KTOT + z * DIM + k] = __float2half_rn(t[threadIdx.x][threadIdx.y]);
}

// ---------------------------------------------------------------------------
// Fused RGCN kernel (round-14 structure + fused LayerNorm epilogue):
// per block, 64 consecutive dst rows.
// Warps 0-7 (tid<256): B-pipelined fp16 MMA over 9 relation-slices consuming
// the double-buffered aggregate A_z. Warps 8-15: aggregate relation z+1 while
// MMA runs relation z. Epilogue: C tile -> smem (AG region), LayerNorm fused,
// normalized rows stored direct. No atomics anywhere.
// ---------------------------------------------------------------------------
__global__ __launch_bounds__(512, 1)
void fused_rgcn(const __half* __restrict__ XH,
                const __half* __restrict__ WB,
                float* __restrict__ out,
                const float* __restrict__ gamma,
                const float* __restrict__ beta)
{
    extern __shared__ char smem[];
    const int tid = threadIdx.x;
    const long long base = (long long)blockIdx.x * TM;

    uint32_t sb;
    asm("{ .reg .u64 t; cvta.to.shared.u64 t, %1; cvt.u32.u64 %0, t; }" : "=r"(sb) : "l"(smem));

    const int lane = tid & 31;
    const int warp = tid >> 5;

    // ---- aggregation (warps 8..15): fill A buffer (zz&1) with relation zz ----
    auto aggregate = [&](int zz) {
        const int awarp = warp - 8;                   // 0..7
        char* Ag = smem + ((zz & 1) ? OFF_AG1 : OFF_AG0);
        #pragma unroll 1
        for (int rr = 0; rr < 8; rr++) {
            int r = awarp * 8 + rr;
            long long d = base + r;
            float acc[8] = {0.f, 0.f, 0.f, 0.f, 0.f, 0.f, 0.f, 0.f};
            if (d < NN) {
                if (zz < 8) {
                    int bin = zz * NN + (int)d;
                    int e0 = g_off0[bin], e1 = g_off[bin];
                    for (int e = e0; e < e1; e++) {
                        int src = g_src32[e];
                        uint4 v = *reinterpret_cast<const uint4*>(
                            (const char*)XH + (size_t)src * 512 + lane * 16);
                        const __half2* h = reinterpret_cast<const __half2*>(&v);
                        #pragma unroll
                        for (int i = 0; i < 4; i++) {
                            float2 f = __half22float2(h[i]);
                            acc[2 * i]     += f.x;
                            acc[2 * i + 1] += f.y;
                        }
                    }
                } else {   // self: copy x[d]
                    uint4 v = *reinterpret_cast<const uint4*>(
                        (const char*)XH + (size_t)d * 512 + lane * 16);
                    const __half2* h = reinterpret_cast<const __half2*>(&v);
                    #pragma unroll
                    for (int i = 0; i < 4; i++) {
                        float2 f = __half22float2(h[i]);
                        acc[2 * i]     += f.x;
                        acc[2 * i + 1] += f.y;
                    }
                }
            }
            __half2 o[4];
            #pragma unroll
            for (int i = 0; i < 4; i++) o[i] = __floats2half2_rn(acc[2 * i], acc[2 * i + 1]);
            *reinterpret_cast<uint4*>(Ag + (size_t)(r * AG_STRIDE + lane * 4) * 4) =
                *reinterpret_cast<const uint4*>(o);
        }
    };

    // ---- MMA-side identifiers ----
    const int wm = warp >> 2;         // 0..1 (MMA warps)
    const int wn = warp & 3;          // 0..3
    const int g  = lane >> 2;         // 0..7
    const int t4 = lane & 3;          // 0..3

    const char* bSrc = (const char*)WB + (size_t)tid * (KTOT * 2);   // n-row = tid (tid<256)
    const uint32_t offB[2] = { sb + OFF_B0, sb + OFF_B1 };

    auto stageB = [&](int kc, int buf) {   // kc = global chunk 0..35
        #pragma unroll
        for (int i = 0; i < 8; i++)
            cp_async16(offB[buf] + tid * (B_STRIDE * 4) + i * 16, bSrc + kc * 128 + i * 16);
    };

    float c[2][8][4];
    #pragma unroll
    for (int mi = 0; mi < 2; mi++)
        #pragma unroll
        for (int j = 0; j < 8; j++)
            #pragma unroll
            for (int q = 0; q < 4; q++)
                c[mi][j][q] = 0.f;

    // ---- prologue ----
    if (tid < 256) {
        stageB(0, 0);
        cp_commit();
    } else {
        aggregate(0);                  // A_0 into buffer 0
    }
    __syncthreads();

    // ---- main loop over relation slices ----
    #pragma unroll 1
    for (int z = 0; z < NZ; z++) {
        if (tid < 256) {
            const unsigned* Ab = (const unsigned*)(smem + ((z & 1) ? OFF_AG1 : OFF_AG0));
            #pragma unroll 1
            for (int kc4 = 0; kc4 < 4; kc4++) {
                const int kc = z * 4 + kc4;
                if (kc + 1 < NCHTOT) stageB(kc + 1, (kc + 1) & 1);
                cp_commit();           // uniform group accounting
                cp_wait1();            // chunk kc's group complete
                barn(1, 256);          // visible to all MMA warps

                const unsigned* Bb = (const unsigned*)(smem + ((kc & 1) ? OFF_B1 : OFF_B0));
                const int abase = kc4 * 32;

                #pragma unroll
                for (int s = 0; s < 4; s++) {
                    unsigned a[2][4], b[8][2];
                    #pragma unroll
                    for (int mi = 0; mi < 2; mi++) {
                        int rb = wm * 32 + mi * 16 + g;
                        a[mi][0] = Ab[(size_t)rb       * AG_STRIDE + abase + s * 8 + t4];
                        a[mi][1] = Ab[(size_t)(rb + 8) * AG_STRIDE + abase + s * 8 + t4];
                        a[mi][2] = Ab[(size_t)rb       * AG_STRIDE + abase + s * 8 + t4 + 4];
                        a[mi][3] = Ab[(size_t)(rb + 8) * AG_STRIDE + abase + s * 8 + t4 + 4];
                    }
                    #pragma unroll
                    for (int j = 0; j < 8; j++) {
                        int n = wn * 64 + j * 8 + g;
                        b[j][0] = Bb[(size_t)n * B_STRIDE + s * 8 + t4];
                        b[j][1] = Bb[(size_t)n * B_STRIDE + s * 8 + t4 + 4];
                    }
                    #pragma unroll
                    for (int mi = 0; mi < 2; mi++)
                        #pragma unroll
                        for (int j = 0; j < 8; j++)
                            mma_f16(c[mi][j], a[mi], b[j]);
                }
                barn(1, 256);          // all MMA warps done reading B buf (WAR)
            }
        } else {
            if (z + 1 < NZ) aggregate(z + 1);   // next relation (or self) into other A buf
        }
        __syncthreads();               // A handoff for z+1
    }

    // ---- epilogue: stage C to smem (AG region now free), fused LayerNorm ----
    float* Cs = (float*)smem;          // [TM][CS_STRIDE] = 66560 B < 67584 B
    if (tid < 256) {
        #pragma unroll
        for (int mi = 0; mi < 2; mi++) {
            #pragma unroll
            for (int half = 0; half < 2; half++) {
                int r = wm * 32 + mi * 16 + half * 8 + g;
                float* rowp = Cs + (size_t)r * CS_STRIDE + wn * 64;
                #pragma unroll
                for (int j = 0; j < 8; j++) {
                    int col = j * 8 + t4 * 2;
                    *reinterpret_cast<float2*>(rowp + col) =
                        make_float2(c[mi][j][half * 2 + 0], c[mi][j][half * 2 + 1]);
                }
            }
        }
    }
    __syncthreads();

    // LayerNorm: 16 warps cover 64 rows (4 rows each)
    {
        float4 g0 = *reinterpret_cast<const float4*>(gamma + lane * 4);
        float4 g1 = *reinterpret_cast<const float4*>(gamma + 128 + lane * 4);
        float4 b0 = *reinterpret_cast<const float4*>(beta + lane * 4);
        float4 b1 = *reinterpret_cast<const float4*>(beta + 128 + lane * 4);

        #pragma unroll 1
        for (int r = warp; r < TM; r += 16) {
            long long drow = base + r;
            if (drow >= NN) continue;
            const float* row = Cs + (size_t)r * CS_STRIDE;
            float4 v0 = *reinterpret_cast<const float4*>(row + lane * 4);
            float4 v1 = *reinterpret_cast<const float4*>(row + 128 + lane * 4);

            float s  = v0.x + v0.y + v0.z + v0.w + v1.x + v1.y + v1.z + v1.w;
            float sq = fmaf(v0.x, v0.x, fmaf(v0.y, v0.y, fmaf(v0.z, v0.z, v0.w * v0.w)))
                     + fmaf(v1.x, v1.x, fmaf(v1.y, v1.y, fmaf(v1.z, v1.z, v1.w * v1.w)));
            #pragma unroll
            for (int o = 16; o; o >>= 1) {
                s  += __shfl_xor_sync(0xffffffffu, s,  o);
                sq += __shfl_xor_sync(0xffffffffu, sq, o);
            }
            float mean = s * (1.f / 256.f);
            float var  = sq * (1.f / 256.f) - mean * mean;
            float rs   = rsqrtf(var + 1e-5f);

            float4 o0, o1;
            o0.x = (v0.x - mean) * rs * g0.x + b0.x;
            o0.y = (v0.y - mean) * rs * g0.y + b0.y;
            o0.z = (v0.z - mean) * rs * g0.z + b0.z;
            o0.w = (v0.w - mean) * rs * g0.w + b0.w;
            o1.x = (v1.x - mean) * rs * g1.x + b1.x;
            o1.y = (v1.y - mean) * rs * g1.y + b1.y;
            o1.z = (v1.z - mean) * rs * g1.z + b1.z;
            o1.w = (v1.w - mean) * rs * g1.w + b1.w;

            float* op = out + (size_t)drow * DIM;
            *reinterpret_cast<float4*>(op + lane * 4)       = o0;
            *reinterpret_cast<float4*>(op + 128 + lane * 4) = o1;
        }
    }
}

extern "C" void kernel_launch(void* const* d_in, const int* in_sizes, int n_in,
                              void* d_out, int out_size)
{
    const float* x     = (const float*)d_in[0];
    const void*  srcb  = d_in[1];
    const void*  dstb  = d_in[2];
    const float* Wself = (const float*)d_in[3];
    const float* Wrel  = (const float*)d_in[4];
    const float* gamma = (const float*)d_in[5];
    const float* beta  = (const float*)d_in[6];
    float* out = (float*)d_out;

    void *pXh = nullptr, *pWB = nullptr;
    cudaGetSymbolAddress(&pXh, g_xh);
    cudaGetSymbolAddress(&pWB, g_Wbig);

    cudaFuncSetAttribute(fused_rgcn,
                         cudaFuncAttributeMaxDynamicSharedMemorySize, SMEM_TOTAL);

    // --- prepass: dtype detect + counting sort of src by (rel, dst) ---
    detect_idx_kernel<<<1, 256>>>(srcb);
    zero_hist_kernel<<<(NBINS + 1023) / 1024, 1024>>>();
    hist_kernel<<<(NEDGES + 255) / 256, 256>>>(dstb);
    scan_local_kernel<<<NSCANBLK, SCAN_BLK>>>();
    scan_bsum_kernel<<<1, SCAN_BLK>>>();
    add_bsum_kernel<<<NSCANBLK, SCAN_BLK>>>();
    copy_off_kernel<<<(NBINS + 1023) / 1024, 1024>>>();
    scatter_kernel<<<(NEDGES + 255) / 256, 256>>>(srcb, dstb);

    // --- conversions ---
    {
        long long nh2 = (long long)NN * DIM / 2;
        x_to_half<<<(int)((nh2 + 255) / 256), 256>>>(x);
        build_wbig<<<dim3(8, 8, NRELS + 1), dim3(32, 32)>>>(Wrel, Wself);
    }

    // --- fused aggregate + GEMM + LayerNorm ---
    fused_rgcn<<<(NN + TM - 1) / TM, 512, SMEM_TOTAL>>>(
        (const __half*)pXh, (const __half*)pWB, out, gamma, beta);
}

// round 17
// speedup vs baseline: 2.0413x; 1.4264x over previous
#include <cuda_runtime.h>
#include <cuda_fp16.h>
#include <cstdint>

#define NN      100000
#define DIM     256
#define NRELS   8
#define EPR     160000
#define NEDGES  (NRELS * EPR)
#define NBINS   (NRELS * NN)

#define KTOT    2304              // 8 relations * 256 + self 256
#define TM      64                // dst rows per block
#define NZ      9                 // 8 relations + self
#define NCHTOT  36                // 9 * 4 K-chunks of 64 halves

// ---- smem layout ----
// A aggregate buffers: 64 rows x 132 words (256 halves + 8 pad halves)
#define AG_STRIDE 132                       // words per row
#define AG_BYTES  (TM * AG_STRIDE * 4)      // 33792
#define OFF_AG0   0
#define OFF_AG1   AG_BYTES
// B staging: 256 n-rows x 36 words (64 halves + 8 pad) = 36864 B per buffer
#define B_STRIDE  36
#define B_BYTES   (DIM * B_STRIDE * 4)      // 36864
#define OFF_B0    (2 * AG_BYTES)            // 67584
#define OFF_B1    (OFF_B0 + B_BYTES)        // 104448
#define OFF_MBAR  (OFF_B1 + B_BYTES)        // 141312 (2 mbarriers, 16 B)
#define SMEM_TOTAL (OFF_MBAR + 16)          // 141328 -> 1 CTA/SM
// C-tile staging for fused LN (reuses AG region): 64 x 260 floats = 66560 B
#define CS_STRIDE 260

// B stage image rows: 72 halves per row (64 data + 8 pad), mirrors smem exactly
#define WS_ROW_H  72

#define SCAN_BLK 1024
#define NSCANBLK ((NBINS + SCAN_BLK - 1) / SCAN_BLK)   // 782

// ---------------------------------------------------------------------------
// device scratch
// ---------------------------------------------------------------------------
__device__ int     g_src32[NEDGES];             // src sorted by (rel, dst)
__device__ int     g_idx_is_i32;
__device__ int     g_off[NBINS];                // end offsets (post-scatter)
__device__ int     g_off0[NBINS];               // start offsets
__device__ int     g_bsum[SCAN_BLK];
__device__ __half2 g_xh[NN * DIM / 2];          // x -> fp16 (51.2MB, L2-resident)
__device__ __half  g_Wbig[DIM * KTOT];          // [n][2304]: {W_rel 0..7, W_self}
__device__ __half  g_Wstage[NCHTOT * DIM * WS_ROW_H];  // padded smem image, 1.33MB

// ---------------------------------------------------------------------------
// helpers
// ---------------------------------------------------------------------------
__device__ __forceinline__ void mma_f16(float c[4], const unsigned a[4], const unsigned b[2]) {
    asm volatile(
        "mma.sync.aligned.m16n8k16.row.col.f32.f16.f16.f32 "
        "{%0,%1,%2,%3}, {%4,%5,%6,%7}, {%8,%9}, {%0,%1,%2,%3};\n"
        : "+f"(c[0]), "+f"(c[1]), "+f"(c[2]), "+f"(c[3])
        : "r"(a[0]), "r"(a[1]), "r"(a[2]), "r"(a[3]), "r"(b[0]), "r"(b[1]));
}

__device__ __forceinline__ void barn(int id, int cnt) {
    asm volatile("bar.sync %0, %1;" :: "r"(id), "r"(cnt) : "memory");
}

__device__ __forceinline__ void mbar_init(uint32_t a, uint32_t cnt) {
    asm volatile("mbarrier.init.shared.b64 [%0], %1;" :: "r"(a), "r"(cnt) : "memory");
}
__device__ __forceinline__ void mbar_expect_tx(uint32_t a, uint32_t bytes) {
    asm volatile("mbarrier.arrive.expect_tx.shared.b64 _, [%0], %1;"
                 :: "r"(a), "r"(bytes) : "memory");
}
__device__ __forceinline__ void mbar_wait(uint32_t a, uint32_t ph) {
    uint32_t done;
    asm volatile(
        "{\n\t.reg .pred p;\n\t"
        "mbarrier.try_wait.parity.acquire.cta.shared::cta.b64 p, [%1], %2;\n\t"
        "selp.b32 %0, 1, 0, p;\n\t}" : "=r"(done) : "r"(a), "r"(ph) : "memory");
    if (!done) {
        asm volatile(
            "{\n\t.reg .pred P1;\n\t"
            "W%=:\n\t"
            "mbarrier.try_wait.parity.acquire.cta.shared::cta.b64 P1, [%0], %1, 0x989680;\n\t"
            "@P1 bra.uni D%=;\n\t"
            "bra.uni W%=;\n\t"
            "D%=:\n\t}" :: "r"(a), "r"(ph) : "memory");
    }
}
__device__ __forceinline__ void bulk_ldg(uint32_t smem_addr, const void* g,
                                         uint32_t bytes, uint32_t mbar) {
    asm volatile(
        "cp.async.bulk.shared::cta.global.mbarrier::complete_tx::bytes [%0], [%1], %2, [%3];"
        :: "r"(smem_addr), "l"(g), "r"(bytes), "r"(mbar) : "memory");
}
#define FENCE_ASYNC() asm volatile("fence.proxy.async.shared::cta;" ::: "memory")

__device__ __forceinline__ int load_idx(const void* buf, long long i) {
    return g_idx_is_i32 ? ((const int*)buf)[i] : (int)((const long long*)buf)[i];
}

// ---------------------------------------------------------------------------
// prepass: dtype detect + counting sort of src by (rel, dst)
// ---------------------------------------------------------------------------
__global__ void detect_idx_kernel(const void* srcbuf) {
    const long long* p = (const long long*)srcbuf;
    int tid = threadIdx.x;
    int bad = 0;
    #pragma unroll
    for (int i = 0; i < 4; i++) {
        long long v = p[tid * 4 + i];
        if (v < 0 || v >= NN) bad = 1;
    }
    int any = __syncthreads_or(bad);
    if (tid == 0) g_idx_is_i32 = any;
}

__global__ void zero_hist_kernel() {
    int i = blockIdx.x * blockDim.x + threadIdx.x;
    if (i < NBINS) g_off[i] = 0;
}

__global__ void hist_kernel(const void* dstbuf) {
    long long i = (long long)blockIdx.x * blockDim.x + threadIdx.x;
    if (i >= NEDGES) return;
    int rel = (int)(i / EPR);
    int dst = load_idx(dstbuf, i);
    atomicAdd(&g_off[rel * NN + dst], 1);
}

__global__ void scan_local_kernel() {
    __shared__ int sh[SCAN_BLK];
    int i = blockIdx.x * SCAN_BLK + threadIdx.x;
    int v = (i < NBINS) ? g_off[i] : 0;
    sh[threadIdx.x] = v;
    __syncthreads();
    #pragma unroll
    for (int o = 1; o < SCAN_BLK; o <<= 1) {
        int t = (threadIdx.x >= o) ? sh[threadIdx.x - o] : 0;
        __syncthreads();
        sh[threadIdx.x] += t;
        __syncthreads();
    }
    if (i < NBINS) g_off[i] = sh[threadIdx.x] - v;   // exclusive
    if (threadIdx.x == SCAN_BLK - 1) g_bsum[blockIdx.x] = sh[threadIdx.x];
}

__global__ void scan_bsum_kernel() {
    __shared__ int sh[SCAN_BLK];
    int v = (threadIdx.x < NSCANBLK) ? g_bsum[threadIdx.x] : 0;
    sh[threadIdx.x] = v;
    __syncthreads();
    #pragma unroll
    for (int o = 1; o < SCAN_BLK; o <<= 1) {
        int t = (threadIdx.x >= o) ? sh[threadIdx.x - o] : 0;
        __syncthreads();
        sh[threadIdx.x] += t;
        __syncthreads();
    }
    if (threadIdx.x < NSCANBLK) g_bsum[threadIdx.x] = sh[threadIdx.x] - v;
}

__global__ void add_bsum_kernel() {
    int i = blockIdx.x * SCAN_BLK + threadIdx.x;
    if (i < NBINS) g_off[i] += g_bsum[blockIdx.x];
}

__global__ void copy_off_kernel() {
    int i = blockIdx.x * blockDim.x + threadIdx.x;
    if (i < NBINS) g_off0[i] = g_off[i];   // start offsets (pre-scatter)
}

__global__ void scatter_kernel(const void* srcbuf, const void* dstbuf) {
    long long i = (long long)blockIdx.x * blockDim.x + threadIdx.x;
    if (i >= NEDGES) return;
    int rel = (int)(i / EPR);
    int src = load_idx(srcbuf, i);
    int dst = load_idx(dstbuf, i);
    int pos = atomicAdd(&g_off[rel * NN + dst], 1);   // bumps to end offsets
    g_src32[pos] = src;
}

// ---------------------------------------------------------------------------
// conversions
// ---------------------------------------------------------------------------
__global__ void x_to_half(const float* __restrict__ x) {
    long long i = (long long)blockIdx.x * blockDim.x + threadIdx.x;
    if (i >= (long long)NN * DIM / 2) return;
    float2 v = ((const float2*)x)[i];
    g_xh[i] = __floats2half2_rn(v.x, v.y);
}

// Wbig[n][z*256 + k] = W_z[k][n];  z = 0..7 -> W_rel[z], z = 8 -> W_self
__global__ void build_wbig(const float* __restrict__ Wrel, const float* __restrict__ Wself) {
    __shared__ float t[32][33];
    int z = blockIdx.z;
    const float* S = (z < NRELS) ? (Wrel + (size_t)z * DIM * DIM) : Wself;
    int bn = blockIdx.x * 32, bk = blockIdx.y * 32;
    t[threadIdx.y][threadIdx.x] = S[(size_t)(bk + threadIdx.y) * DIM + bn + threadIdx.x];
    __syncthreads();
    int n = bn + threadIdx.y, k = bk + threadIdx.x;
    g_Wbig[(size_t)n * KTOT + z * DIM + k] = __float2half_rn(t[threadIdx.x][threadIdx.y]);
}

// Build the padded smem image: Wstage[(kc*256+n)*72 + h] = Wbig[n*2304 + kc*64 + h]
__global__ void build_wstage() {
    int i = blockIdx.x * blockDim.x + threadIdx.x;   // NCHTOT*256*8 vec16 copies
    if (i >= NCHTOT * DIM * 8) return;
    int vec = i & 7;
    int rn  = i >> 3;              // kc*256 + n
    int kc  = rn >> 8;
    int n   = rn & 255;
    const uint4* s = reinterpret_cast<const uint4*>(
        g_Wbig + (size_t)n * KTOT + kc * 64) + vec;
    uint4* d = reinterpret_cast<uint4*>(
        g_Wstage + (size_t)rn * WS_ROW_H) + vec;
    *d = *s;
}

// ---------------------------------------------------------------------------
// Fused RGCN kernel: per block, 64 consecutive dst rows.
// Warps 0-7 (tid<256): fp16 MMA over 9 relation-slices, B tiles delivered by
// cp.async.bulk (1 op / 36KB chunk, mbarrier completion) from the padded
// g_Wstage image. Warps 8-15: aggregate relation z+1 while MMA runs z.
// Epilogue: C -> smem, fused LayerNorm, direct stores. No atomics.
// ---------------------------------------------------------------------------
__global__ __launch_bounds__(512, 1)
void fused_rgcn(const __half* __restrict__ XH,
                float* __restrict__ out,
                const float* __restrict__ gamma,
                const float* __restrict__ beta)
{
    extern __shared__ char smem[];
    const int tid = threadIdx.x;
    const long long base = (long long)blockIdx.x * TM;

    uint32_t sb;
    asm("{ .reg .u64 t; cvta.to.shared.u64 t, %1; cvt.u32.u64 %0, t; }" : "=r"(sb) : "l"(smem));

    const int lane = tid & 31;
    const int warp = tid >> 5;

    const uint32_t offB[2] = { sb + OFF_B0, sb + OFF_B1 };
    const uint32_t mbar[2] = { sb + OFF_MBAR, sb + OFF_MBAR + 8 };

    // stage chunk kc into buffer kc&1 (single thread)
    auto stage_chunk = [&](int kc) {
        int buf = kc & 1;
        mbar_expect_tx(mbar[buf], B_BYTES);
        bulk_ldg(offB[buf], (const char*)g_Wstage + (size_t)kc * B_BYTES,
                 B_BYTES, mbar[buf]);
    };

    // ---- aggregation (warps 8..15): fill A buffer (zz&1) with relation zz ----
    auto aggregate = [&](int zz) {
        const int awarp = warp - 8;                   // 0..7
        char* Ag = smem + ((zz & 1) ? OFF_AG1 : OFF_AG0);
        #pragma unroll 1
        for (int rr = 0; rr < 8; rr++) {
            int r = awarp * 8 + rr;
            long long d = base + r;
            float acc[8] = {0.f, 0.f, 0.f, 0.f, 0.f, 0.f, 0.f, 0.f};
            if (d < NN) {
                if (zz < 8) {
                    int bin = zz * NN + (int)d;
                    int e0 = g_off0[bin], e1 = g_off[bin];
                    for (int e = e0; e < e1; e++) {
                        int src = g_src32[e];
                        uint4 v = *reinterpret_cast<const uint4*>(
                            (const char*)XH + (size_t)src * 512 + lane * 16);
                        const __half2* h = reinterpret_cast<const __half2*>(&v);
                        #pragma unroll
                        for (int i = 0; i < 4; i++) {
                            float2 f = __half22float2(h[i]);
                            acc[2 * i]     += f.x;
                            acc[2 * i + 1] += f.y;
                        }
                    }
                } else {   // self: copy x[d]
                    uint4 v = *reinterpret_cast<const uint4*>(
                        (const char*)XH + (size_t)d * 512 + lane * 16);
                    const __half2* h = reinterpret_cast<const __half2*>(&v);
                    #pragma unroll
                    for (int i = 0; i < 4; i++) {
                        float2 f = __half22float2(h[i]);
                        acc[2 * i]     += f.x;
                        acc[2 * i + 1] += f.y;
                    }
                }
            }
            __half2 o[4];
            #pragma unroll
            for (int i = 0; i < 4; i++) o[i] = __floats2half2_rn(acc[2 * i], acc[2 * i + 1]);
            *reinterpret_cast<uint4*>(Ag + (size_t)(r * AG_STRIDE + lane * 4) * 4) =
                *reinterpret_cast<const uint4*>(o);
        }
    };

    // ---- MMA-side identifiers ----
    const int wm = warp >> 2;         // 0..1 (MMA warps)
    const int wn = warp & 3;          // 0..3
    const int g  = lane >> 2;         // 0..7
    const int t4 = lane & 3;          // 0..3

    float c[2][8][4];
    #pragma unroll
    for (int mi = 0; mi < 2; mi++)
        #pragma unroll
        for (int j = 0; j < 8; j++)
            #pragma unroll
            for (int q = 0; q < 4; q++)
                c[mi][j][q] = 0.f;

    // ---- prologue ----
    if (tid == 0) {
        mbar_init(mbar[0], 1);
        mbar_init(mbar[1], 1);
        FENCE_ASYNC();
    }
    __syncthreads();                   // mbarriers visible before any bulk
    if (tid == 0) {
        stage_chunk(0);
        stage_chunk(1);
    }
    if (warp >= 8) aggregate(0);       // A_0 into buffer 0
    __syncthreads();                   // A_0 visible

    // ---- main loop over relation slices ----
    #pragma unroll 1
    for (int z = 0; z < NZ; z++) {
        if (tid < 256) {
            const unsigned* Ab = (const unsigned*)(smem + ((z & 1) ? OFF_AG1 : OFF_AG0));
            #pragma unroll 1
            for (int kc4 = 0; kc4 < 4; kc4++) {
                const int kc = z * 4 + kc4;
                mbar_wait(mbar[kc & 1], (kc >> 1) & 1);   // B chunk kc ready

                const unsigned* Bb = (const unsigned*)(smem + ((kc & 1) ? OFF_B1 : OFF_B0));
                const int abase = kc4 * 32;

                #pragma unroll
                for (int s = 0; s < 4; s++) {
                    unsigned a[2][4], b[8][2];
                    #pragma unroll
                    for (int mi = 0; mi < 2; mi++) {
                        int rb = wm * 32 + mi * 16 + g;
                        a[mi][0] = Ab[(size_t)rb       * AG_STRIDE + abase + s * 8 + t4];
                        a[mi][1] = Ab[(size_t)(rb + 8) * AG_STRIDE + abase + s * 8 + t4];
                        a[mi][2] = Ab[(size_t)rb       * AG_STRIDE + abase + s * 8 + t4 + 4];
                        a[mi][3] = Ab[(size_t)(rb + 8) * AG_STRIDE + abase + s * 8 + t4 + 4];
                    }
                    #pragma unroll
                    for (int j = 0; j < 8; j++) {
                        int n = wn * 64 + j * 8 + g;
                        b[j][0] = Bb[(size_t)n * B_STRIDE + s * 8 + t4];
                        b[j][1] = Bb[(size_t)n * B_STRIDE + s * 8 + t4 + 4];
                    }
                    #pragma unroll
                    for (int mi = 0; mi < 2; mi++)
                        #pragma unroll
                        for (int j = 0; j < 8; j++)
                            mma_f16(c[mi][j], a[mi], b[j]);
                }
                barn(1, 256);          // all MMA warps done reading buf kc&1 (WAR)
                if (tid == 0 && kc + 2 < NCHTOT) stage_chunk(kc + 2);
            }
        } else {
            if (z + 1 < NZ) aggregate(z + 1);   // next relation (or self) into other A buf
        }
        __syncthreads();               // A handoff for z+1
    }

    // ---- epilogue: stage C to smem (AG region now free), fused LayerNorm ----
    float* Cs = (float*)smem;          // [TM][CS_STRIDE] = 66560 B < 67584 B
    if (tid < 256) {
        #pragma unroll
        for (int mi = 0; mi < 2; mi++) {
            #pragma unroll
            for (int half = 0; half < 2; half++) {
                int r = wm * 32 + mi * 16 + half * 8 + g;
                float* rowp = Cs + (size_t)r * CS_STRIDE + wn * 64;
                #pragma unroll
                for (int j = 0; j < 8; j++) {
                    int col = j * 8 + t4 * 2;
                    *reinterpret_cast<float2*>(rowp + col) =
                        make_float2(c[mi][j][half * 2 + 0], c[mi][j][half * 2 + 1]);
                }
            }
        }
    }
    __syncthreads();

    // LayerNorm: 16 warps cover 64 rows (4 rows each)
    {
        float4 g0 = *reinterpret_cast<const float4*>(gamma + lane * 4);
        float4 g1 = *reinterpret_cast<const float4*>(gamma + 128 + lane * 4);
        float4 b0 = *reinterpret_cast<const float4*>(beta + lane * 4);
        float4 b1 = *reinterpret_cast<const float4*>(beta + 128 + lane * 4);

        #pragma unroll 1
        for (int r = warp; r < TM; r += 16) {
            long long drow = base + r;
            if (drow >= NN) continue;
            const float* row = Cs + (size_t)r * CS_STRIDE;
            float4 v0 = *reinterpret_cast<const float4*>(row + lane * 4);
            float4 v1 = *reinterpret_cast<const float4*>(row + 128 + lane * 4);

            float s  = v0.x + v0.y + v0.z + v0.w + v1.x + v1.y + v1.z + v1.w;
            float sq = fmaf(v0.x, v0.x, fmaf(v0.y, v0.y, fmaf(v0.z, v0.z, v0.w * v0.w)))
                     + fmaf(v1.x, v1.x, fmaf(v1.y, v1.y, fmaf(v1.z, v1.z, v1.w * v1.w)));
            #pragma unroll
            for (int o = 16; o; o >>= 1) {
                s  += __shfl_xor_sync(0xffffffffu, s,  o);
                sq += __shfl_xor_sync(0xffffffffu, sq, o);
            }
            float mean = s * (1.f / 256.f);
            float var  = sq * (1.f / 256.f) - mean * mean;
            float rs   = rsqrtf(var + 1e-5f);

            float4 o0, o1;
            o0.x = (v0.x - mean) * rs * g0.x + b0.x;
            o0.y = (v0.y - mean) * rs * g0.y + b0.y;
            o0.z = (v0.z - mean) * rs * g0.z + b0.z;
            o0.w = (v0.w - mean) * rs * g0.w + b0.w;
            o1.x = (v1.x - mean) * rs * g1.x + b1.x;
            o1.y = (v1.y - mean) * rs * g1.y + b1.y;
            o1.z = (v1.z - mean) * rs * g1.z + b1.z;
            o1.w = (v1.w - mean) * rs * g1.w + b1.w;

            float* op = out + (size_t)drow * DIM;
            *reinterpret_cast<float4*>(op + lane * 4)       = o0;
            *reinterpret_cast<float4*>(op + 128 + lane * 4) = o1;
        }
    }
}

extern "C" void kernel_launch(void* const* d_in, const int* in_sizes, int n_in,
                              void* d_out, int out_size)
{
    const float* x     = (const float*)d_in[0];
    const void*  srcb  = d_in[1];
    const void*  dstb  = d_in[2];
    const float* Wself = (const float*)d_in[3];
    const float* Wrel  = (const float*)d_in[4];
    const float* gamma = (const float*)d_in[5];
    const float* beta  = (const float*)d_in[6];
    float* out = (float*)d_out;

    void *pXh = nullptr;
    cudaGetSymbolAddress(&pXh, g_xh);

    cudaFuncSetAttribute(fused_rgcn,
                         cudaFuncAttributeMaxDynamicSharedMemorySize, SMEM_TOTAL);

    // --- prepass: dtype detect + counting sort of src by (rel, dst) ---
    detect_idx_kernel<<<1, 256>>>(srcb);
    zero_hist_kernel<<<(NBINS + 1023) / 1024, 1024>>>();
    hist_kernel<<<(NEDGES + 255) / 256, 256>>>(dstb);
    scan_local_kernel<<<NSCANBLK, SCAN_BLK>>>();
    scan_bsum_kernel<<<1, SCAN_BLK>>>();
    add_bsum_kernel<<<NSCANBLK, SCAN_BLK>>>();
    copy_off_kernel<<<(NBINS + 1023) / 1024, 1024>>>();
    scatter_kernel<<<(NEDGES + 255) / 256, 256>>>(srcb, dstb);

    // --- conversions ---
    {
        long long nh2 = (long long)NN * DIM / 2;
        x_to_half<<<(int)((nh2 + 255) / 256), 256>>>(x);
        build_wbig<<<dim3(8, 8, NRELS + 1), dim3(32, 32)>>>(Wrel, Wself);
        int nws = NCHTOT * DIM * 8;
        build_wstage<<<(nws + 255) / 256, 256>>>();
    }

    // --- fused aggregate + GEMM + LayerNorm ---
    fused_rgcn<<<(NN + TM - 1) / TM, 512, SMEM_TOTAL>>>(
        (const __half*)pXh, out, gamma, beta);
}